// round 2
// baseline (speedup 1.0000x reference)
#include <cuda_runtime.h>
#include <cuda_bf16.h>

// InverseLeakySoftplus: solve a*x + (1-a)*softplus(x) = y for x, per element.
// a = 0.1 + 0.4*sigmoid(raw_alpha[0]).
// Newton with the reference's init; 6 iterations reach fp32 fixed point
// (worst case y->0+ needs ~5; quadratic convergence, contraction < 0.78).
//
// Per iteration: 3 MUFU (EX2, LG2, RCP) + ~12 FMA/ALU. MUFU and FMA pipes
// are balanced at ~0.19 cyc/elem/SM each, so this is jointly compute-bound.

#define NITERS 6

__device__ __forceinline__ float newton_inverse(float y, float a, float oma, float inva)
{
    // init: f(x) ~ x for x>>0, f(x) ~ a*x for x<<0
    float x = (y > 0.0f) ? y : y * inva;
#pragma unroll
    for (int it = 0; it < NITERS; ++it) {
        float e  = __expf(-fabsf(x));          // e = exp(-|x|) in (0,1]
        float op = 1.0f + e;
        float sp = __logf(op) + fmaxf(x, 0.0f); // stable softplus
        float fx = fmaf(a, x, oma * sp);        // f(x)
        // f'(x) = (x>=0) ? (1+a*e)/(1+e) : (a+e)/(1+e)
        float num = (x >= 0.0f) ? fmaf(a, e, 1.0f) : (a + e);
        float step = (fx - y) * op * __fdividef(1.0f, num);
        x = x - step;
    }
    return x;
}

__device__ __forceinline__ float compute_alpha(const float* __restrict__ raw_alpha)
{
    float r = __ldg(raw_alpha);
    float sig = __fdividef(1.0f, 1.0f + __expf(-r));
    return fmaf(0.4f, sig, 0.1f);
}

__global__ void inv_lsp_vec4(const float4* __restrict__ in,
                             const float* __restrict__ raw_alpha,
                             float4* __restrict__ out, int n4)
{
    int i = blockIdx.x * blockDim.x + threadIdx.x;
    if (i >= n4) return;

    float a    = compute_alpha(raw_alpha);
    float oma  = 1.0f - a;
    float inva = __fdividef(1.0f, a);

    float4 v = in[i];
    float4 r;
    r.x = newton_inverse(v.x, a, oma, inva);
    r.y = newton_inverse(v.y, a, oma, inva);
    r.z = newton_inverse(v.z, a, oma, inva);
    r.w = newton_inverse(v.w, a, oma, inva);
    out[i] = r;
}

__global__ void inv_lsp_scalar_tail(const float* __restrict__ in,
                                    const float* __restrict__ raw_alpha,
                                    float* __restrict__ out,
                                    int start, int n)
{
    int i = start + blockIdx.x * blockDim.x + threadIdx.x;
    if (i >= n) return;
    float a    = compute_alpha(raw_alpha);
    float oma  = 1.0f - a;
    float inva = __fdividef(1.0f, a);
    out[i] = newton_inverse(in[i], a, oma, inva);
}

extern "C" void kernel_launch(void* const* d_in, const int* in_sizes, int n_in,
                              void* d_out, int out_size)
{
    const float* in        = (const float*)d_in[0];
    const float* raw_alpha = (const float*)d_in[1];
    float* out             = (float*)d_out;
    int n = in_sizes[0];

    int n4 = n / 4;
    if (n4 > 0) {
        int threads = 256;
        int blocks  = (n4 + threads - 1) / threads;
        inv_lsp_vec4<<<blocks, threads>>>((const float4*)in, raw_alpha,
                                          (float4*)out, n4);
    }
    int rem = n - n4 * 4;
    if (rem > 0) {
        inv_lsp_scalar_tail<<<1, 256>>>(in, raw_alpha, out, n4 * 4, n);
    }
}

// round 3
// speedup vs baseline: 1.3446x; 1.3446x over previous
#include <cuda_runtime.h>
#include <cuda_bf16.h>

// InverseLeakySoftplus: solve a*x + (1-a)*softplus(x) = y for x, per element.
// a = 0.1 + 0.4*sigmoid(raw_alpha[0]).
//
// R2 calibration: kernel is MUFU-bound (EX2+LG2+RCP = 3 MUFU/iter @ rt 8/SMSP
// = 24 cyc/iter/elem-warp; 6 iters -> 144 cyc -> 136us measured). Reduce MUFU:
// Newton contraction C = f''/2f' <= 0.23; worst-case init error 1.4 (y->0+)
// gives errors 1.4 -> 0.35 -> 0.027 -> 2e-4 -> <=1e-7 after 4 iterations.
// 4 iters leaves ~4 orders of margin vs the 1e-3 threshold.

#define NITERS 4

__device__ __forceinline__ float newton_inverse(float y, float a, float oma, float inva)
{
    // init: f(x) ~ x for x>>0, f(x) ~ a*x for x<<0
    float x = (y > 0.0f) ? y : y * inva;
#pragma unroll
    for (int it = 0; it < NITERS; ++it) {
        float e  = __expf(-fabsf(x));            // EX2 (+1 FMUL)
        float op = 1.0f + e;
        float sp = __logf(op) + fmaxf(x, 0.0f);  // LG2 (+1 FMUL); stable softplus
        float fx = fmaf(a, x, oma * sp);         // f(x)
        // f'(x) = (x>=0) ? (1+a*e)/(1+e) : (a+e)/(1+e)
        float num = (x >= 0.0f) ? fmaf(a, e, 1.0f) : (a + e);
        x -= __fdividef((fx - y) * op, num);     // RCP (+2 FMUL)
    }
    return x;
}

__global__ void inv_lsp_vec4(const float4* __restrict__ in,
                             const float* __restrict__ raw_alpha,
                             float4* __restrict__ out, int n4)
{
    __shared__ float s_a, s_oma, s_inva;
    if (threadIdx.x == 0) {
        float r   = __ldg(raw_alpha);
        float sig = __fdividef(1.0f, 1.0f + __expf(-r));
        float a   = fmaf(0.4f, sig, 0.1f);
        s_a = a; s_oma = 1.0f - a; s_inva = __fdividef(1.0f, a);
    }
    __syncthreads();

    int i = blockIdx.x * blockDim.x + threadIdx.x;
    if (i >= n4) return;

    float a = s_a, oma = s_oma, inva = s_inva;

    float4 v = in[i];
    float4 r;
    r.x = newton_inverse(v.x, a, oma, inva);
    r.y = newton_inverse(v.y, a, oma, inva);
    r.z = newton_inverse(v.z, a, oma, inva);
    r.w = newton_inverse(v.w, a, oma, inva);
    out[i] = r;
}

__global__ void inv_lsp_scalar_tail(const float* __restrict__ in,
                                    const float* __restrict__ raw_alpha,
                                    float* __restrict__ out,
                                    int start, int n)
{
    int i = start + blockIdx.x * blockDim.x + threadIdx.x;
    if (i >= n) return;
    float r   = __ldg(raw_alpha);
    float sig = __fdividef(1.0f, 1.0f + __expf(-r));
    float a   = fmaf(0.4f, sig, 0.1f);
    float oma = 1.0f - a;
    float inva = __fdividef(1.0f, a);
    out[i] = newton_inverse(in[i], a, oma, inva);
}

extern "C" void kernel_launch(void* const* d_in, const int* in_sizes, int n_in,
                              void* d_out, int out_size)
{
    const float* in        = (const float*)d_in[0];
    const float* raw_alpha = (const float*)d_in[1];
    float* out             = (float*)d_out;
    int n = in_sizes[0];

    int n4 = n / 4;
    if (n4 > 0) {
        int threads = 256;
        int blocks  = (n4 + threads - 1) / threads;
        inv_lsp_vec4<<<blocks, threads>>>((const float4*)in, raw_alpha,
                                          (float4*)out, n4);
    }
    int rem = n - n4 * 4;
    if (rem > 0) {
        inv_lsp_scalar_tail<<<1, 256>>>(in, raw_alpha, out, n4 * 4, n);
    }
}

// round 4
// speedup vs baseline: 2.1989x; 1.6353x over previous
#include <cuda_runtime.h>
#include <cuda_bf16.h>

// InverseLeakySoftplus: solve a*x + (1-a)*softplus(x) = y, a = 0.1+0.4*sigmoid(raw_alpha).
//
// R3 calibration: MUFU-bound, dur ~= 0.73*(MUFU cyc/elem-warp) + 31us.
// Strategy: near-exact init (runtime lerp table of the inverse over the curved
// region, asymptotic inits outside; init err <= 5e-3 everywhere), then ONE
// Halley iteration (cubic: err -> ~1e-8 abs, below fp32 resolution).
// Halley's correction needs no extra MUFU: 3 MUFU/elem total (EX2, LG2, RCP).

#define NSEG 90
#define TPB  256
#define IPT  2              // float4 items per thread

static __constant__ const float kH      = 0.07f;
#define H_F      0.07f
#define INV_H    (1.0f / 0.07f)
#define YMIN_T   (-1.05f)            // table start
#define YMAX_R   (5.2f)              // above: x0 = y        (err <= 4.7e-3)
#define YMIN_R   (-1.0f)             // below: x0 = y/a      (err <= 4.2e-3)

__device__ float g_tab[NSEG + 1];
__device__ float g_consts[3];        // a, 1-a, 1/a

// ---------------- table builder: 1 block, <1us ----------------
__global__ void build_table(const float* __restrict__ raw_alpha)
{
    int k = threadIdx.x;
    float r   = __ldg(raw_alpha);
    float sig = __fdividef(1.0f, 1.0f + __expf(-r));
    float a   = fmaf(0.4f, sig, 0.1f);
    float oma = 1.0f - a;
    float inva = __fdividef(1.0f, a);
    if (k == 0) { g_consts[0] = a; g_consts[1] = oma; g_consts[2] = inva; }
    if (k <= NSEG) {
        float y = YMIN_T + (float)k * H_F;
        float x = (y > 0.0f) ? y : y * inva;
#pragma unroll
        for (int it = 0; it < 8; ++it) {          // to fp32 fixed point
            float e  = __expf(-fabsf(x));
            float op = 1.0f + e;
            float sp = __logf(op) + fmaxf(x, 0.0f);
            float fx = fmaf(a, x, oma * sp);
            float num = (x >= 0.0f) ? fmaf(a, e, 1.0f) : (a + e);
            x -= __fdividef((fx - y) * op, num);
        }
        g_tab[k] = x;
    }
}

// ---------------- per-element solve: table init + 1 Halley ----------------
__device__ __forceinline__ float solve1(float y, float a, float oma, float inva,
                                        const float* __restrict__ s_tab)
{
    // lerp init (clamped; overridden by asymptotic inits outside the table)
    float t = (y - YMIN_T) * INV_H;
    t = fminf(fmaxf(t, 0.0f), (float)NSEG - 0.0005f);
    int   k  = (int)t;
    float fr = t - (float)k;
    float xl = s_tab[k];
    float x0 = fmaf(fr, s_tab[k + 1] - xl, xl);
    x0 = (y >= YMAX_R) ? y        : x0;
    x0 = (y <= YMIN_R) ? y * inva : x0;

    // one Halley iteration (3 MUFU: EX2, LG2, RCP)
    float e   = __expf(-fabsf(x0));
    float op  = 1.0f + e;
    float sp  = __logf(op) + fmaxf(x0, 0.0f);       // stable softplus
    float fy  = fmaf(a, x0, oma * sp) - y;          // f(x0) - y
    float num = (x0 >= 0.0f) ? fmaf(a, e, 1.0f) : (a + e);  // f' = num/op
    float rn  = __fdividef(1.0f, num);
    float d   = fy * op * rn;                       // Newton step f/f'
    float h2  = 0.5f * oma * e * fy * rn * rn;      // (f/f')*f''/(2f')
    return (x0 - d) - d * h2;                       // x0 - d*(1+h2)
}

__global__ void inv_lsp_main(const float4* __restrict__ in,
                             float4* __restrict__ out, int n4)
{
    __shared__ float s_tab[NSEG + 1];
    __shared__ float s_c[3];
    if (threadIdx.x < NSEG + 1) s_tab[threadIdx.x] = g_tab[threadIdx.x];
    if (threadIdx.x < 3)        s_c[threadIdx.x]   = g_consts[threadIdx.x];
    __syncthreads();
    float a = s_c[0], oma = s_c[1], inva = s_c[2];

    int base = blockIdx.x * (TPB * IPT) + threadIdx.x;
#pragma unroll
    for (int j = 0; j < IPT; ++j) {
        int i = base + j * TPB;
        if (i < n4) {
            float4 v = in[i];
            float4 rr;
            rr.x = solve1(v.x, a, oma, inva, s_tab);
            rr.y = solve1(v.y, a, oma, inva, s_tab);
            rr.z = solve1(v.z, a, oma, inva, s_tab);
            rr.w = solve1(v.w, a, oma, inva, s_tab);
            out[i] = rr;
        }
    }
}

// scalar tail (n divisible by 4 for this problem, but keep it safe)
__global__ void inv_lsp_scalar_tail(const float* __restrict__ in,
                                    float* __restrict__ out,
                                    int start, int n)
{
    int i = start + blockIdx.x * blockDim.x + threadIdx.x;
    if (i >= n) return;
    float a = g_consts[0], oma = g_consts[1], inva = g_consts[2];
    float y = in[i];
    float x = (y > 0.0f) ? y : y * inva;
#pragma unroll
    for (int it = 0; it < 6; ++it) {
        float e  = __expf(-fabsf(x));
        float op = 1.0f + e;
        float sp = __logf(op) + fmaxf(x, 0.0f);
        float fx = fmaf(a, x, oma * sp);
        float num = (x >= 0.0f) ? fmaf(a, e, 1.0f) : (a + e);
        x -= __fdividef((fx - y) * op, num);
    }
    out[i] = x;
}

extern "C" void kernel_launch(void* const* d_in, const int* in_sizes, int n_in,
                              void* d_out, int out_size)
{
    const float* in        = (const float*)d_in[0];
    const float* raw_alpha = (const float*)d_in[1];
    float* out             = (float*)d_out;
    int n = in_sizes[0];

    build_table<<<1, 128>>>(raw_alpha);

    int n4 = n / 4;
    if (n4 > 0) {
        int per_block = TPB * IPT;
        int blocks = (n4 + per_block - 1) / per_block;
        inv_lsp_main<<<blocks, TPB>>>((const float4*)in, (float4*)out, n4);
    }
    int rem = n - n4 * 4;
    if (rem > 0) {
        inv_lsp_scalar_tail<<<1, 256>>>(in, out, n4 * 4, n);
    }
}